// round 15
// baseline (speedup 1.0000x reference)
#include <cuda_runtime.h>
#include <stdint.h>
#include <math.h>

#define B    8
#define C    64
#define T    4096
#define KNN  9

typedef unsigned long long u64;
typedef unsigned int       u32;

// Scratch (allocation-free: __device__ globals)
__device__ float g_qT[B * T * C];      // normalized q fp32 [b][t][c]
__device__ float g_kT[B * T * C];      // normalized k fp32
__device__ float g_vT[B * T * C];      // v fp32
__device__ float g_wP[KNN * C * C];    // conv_w permuted [kk][cc][o]
__device__ int   g_idx[B * T * KNN];   // top-9 indices per (b,i)
__device__ float g_pv[B * T * 8 * 9];  // partial top-9 values per (row, jsplit)
__device__ int   g_pj[B * T * 8 * 9];  // partial top-9 indices

// ---------------------------------------------------------------------------
__device__ __forceinline__ u64 pk2(float lo, float hi) {
    u64 r; asm("mov.b64 %0, {%1, %2};" : "=l"(r) : "f"(lo), "f"(hi)); return r;
}
__device__ __forceinline__ u64 fma2(u64 a, u64 b, u64 c) {
    u64 d; asm("fma.rn.f32x2 %0, %1, %2, %3;" : "=l"(d) : "l"(a), "l"(b), "l"(c));
    return d;
}
__device__ __forceinline__ void unpk(u64 v, float& lo, float& hi) {
    asm("mov.b64 {%0, %1}, %2;" : "=f"(lo), "=f"(hi) : "l"(v));
}

// ---------------------------------------------------------------------------
__global__ void permute_w_kernel(const float* __restrict__ conv_w) {
    int s = blockIdx.x * 256 + threadIdx.x;
    if (s < KNN * C * C) {
        int o  = s & 63;
        int cc = (s >> 6) & 63;
        int kk = s >> 12;
        g_wP[s] = conv_w[o * (C * KNN) + cc * KNN + kk];
    }
}

// ---------------------------------------------------------------------------
// Kernel 1: projections + L2 normalize (q,k); fp32 outputs (R3-validated).
// ---------------------------------------------------------------------------
__global__ __launch_bounds__(128) void proj_kernel(
    const float* __restrict__ x,
    const float* __restrict__ Wq,
    const float* __restrict__ Wk,
    const float* __restrict__ Wv)
{
    __shared__ float Xs[C][128];
    __shared__ float Ws[C][C];

    const int b   = blockIdx.y;
    const int t0  = blockIdx.x * 128;
    const int tid = threadIdx.x;

    const float* xb = x + (size_t)b * C * T;
    for (int c = 0; c < C; c++)
        Xs[c][tid] = xb[c * T + t0 + tid];

    for (int m = 0; m < 3; m++) {
        const float* W = (m == 0) ? Wq : ((m == 1) ? Wk : Wv);
        float* dstbase = (m == 0) ? g_qT : ((m == 1) ? g_kT : g_vT);

        __syncthreads();
        for (int s = tid; s < C * C; s += 128) {
            int c = s >> 6, d = s & 63;
            Ws[c][d] = W[d * C + c];
        }
        __syncthreads();

        float acc[C];
        #pragma unroll
        for (int d = 0; d < C; d++) acc[d] = 0.f;

        for (int c = 0; c < C; c++) {
            float xv = Xs[c][tid];
            const float4* wr = (const float4*)Ws[c];
            #pragma unroll
            for (int d4 = 0; d4 < 16; d4++) {
                float4 w = wr[d4];
                acc[4*d4+0] = __fmaf_rn(w.x, xv, acc[4*d4+0]);
                acc[4*d4+1] = __fmaf_rn(w.y, xv, acc[4*d4+1]);
                acc[4*d4+2] = __fmaf_rn(w.z, xv, acc[4*d4+2]);
                acc[4*d4+3] = __fmaf_rn(w.w, xv, acc[4*d4+3]);
            }
        }

        if (m < 2) {
            float ss = 0.f;
            #pragma unroll
            for (int d = 0; d < C; d++)
                ss = __fadd_rn(ss, __fmul_rn(acc[d], acc[d]));
            float n = fmaxf(sqrtf(ss), 1e-12f);
            #pragma unroll
            for (int d = 0; d < C; d++)
                acc[d] = __fdiv_rn(acc[d], n);
        }

        float4* dst = (float4*)(dstbase + ((size_t)b * T + t0 + tid) * C);
        #pragma unroll
        for (int d4 = 0; d4 < 16; d4++)
            dst[d4] = make_float4(acc[4*d4+0], acc[4*d4+1], acc[4*d4+2], acc[4*d4+3]);
    }
}

// ---------------------------------------------------------------------------
// Kernel 2a: register-blocked exact sim sweep (4i x 8j per thread).
// CTA: 512 threads = (64 thr-i x 8 thr-j); i-tile 256 rows; full j sweep.
// kX/qX channel-major in smem. Each (i,j) dot = sequential __fmaf_rn chain
// over c=0..63 (bitwise reference ranking). Per-thread per-row top-9 with
// v8 register gate + local-memory list; partials written to global.
// ---------------------------------------------------------------------------
#define SIM_SMEM (64 * 256 * 4 + 64 * 64 * 4)   // kX 64KB + qX 16KB

__global__ __launch_bounds__(512) void sim_sweep_kernel()
{
    extern __shared__ __align__(16) float smem[];
    float* kX = smem;                 // [c][256]
    float* qX = smem + 64 * 256;      // [c][64]

    const int    tid  = threadIdx.x;
    const int    tidi = tid >> 3;     // 0..63
    const int    tidj = tid & 7;      // 0..7
    const int    b    = blockIdx.y;
    const int    i0   = blockIdx.x * 256;
    const size_t bT   = (size_t)b * T;

    // ---- stage kX (once): 256 rows x 16 float4 ----
    #pragma unroll
    for (int u = 0; u < 8; u++) {
        int idx = u * 512 + tid;          // 0..4095
        int row = idx & 255;
        int c4  = idx >> 8;               // 0..15
        float4 v = __ldg((const float4*)(g_kT + (bT + i0 + row) * C) + c4);
        kX[(c4 * 4 + 0) * 256 + row] = v.x;
        kX[(c4 * 4 + 1) * 256 + row] = v.y;
        kX[(c4 * 4 + 2) * 256 + row] = v.z;
        kX[(c4 * 4 + 3) * 256 + row] = v.w;
    }

    // per-row top-9 state: v8 gate in regs, lists in local
    float vv[4] = {-1.f, -1.f, -1.f, -1.f};
    float tlv[36];
    int   tlj[36];
    #pragma unroll 1
    for (int z = 0; z < 36; z++) { tlv[z] = -1.f; tlj[z] = 0x7FFFFFFF; }

    for (int jt = 0; jt < T; jt += 64) {
        __syncthreads();
        // stage qX: 64 rows x 16 float4
        #pragma unroll
        for (int u = 0; u < 2; u++) {
            int idx = u * 512 + tid;      // 0..1023
            int row = idx & 63;
            int c4  = idx >> 6;           // 0..15
            float4 v = __ldg((const float4*)(g_qT + (bT + jt + row) * C) + c4);
            qX[(c4 * 4 + 0) * 64 + row] = v.x;
            qX[(c4 * 4 + 1) * 64 + row] = v.y;
            qX[(c4 * 4 + 2) * 64 + row] = v.z;
            qX[(c4 * 4 + 3) * 64 + row] = v.w;
        }
        __syncthreads();

        float acc[4][8];
        #pragma unroll
        for (int ri = 0; ri < 4; ri++)
            #pragma unroll
            for (int rj = 0; rj < 8; rj++) acc[ri][rj] = 0.f;

        const float* kp = kX + tidi * 4;
        const float* qp = qX + tidj * 8;
        #pragma unroll 8
        for (int c = 0; c < C; c++) {
            float4 kv = *(const float4*)(kp + c * 256);
            float4 q0 = *(const float4*)(qp + c * 64);
            float4 q1 = *(const float4*)(qp + c * 64 + 4);
            float qv[8] = {q0.x, q0.y, q0.z, q0.w, q1.x, q1.y, q1.z, q1.w};
            float ks[4] = {kv.x, kv.y, kv.z, kv.w};
            #pragma unroll
            for (int ri = 0; ri < 4; ri++)
                #pragma unroll
                for (int rj = 0; rj < 8; rj++)
                    acc[ri][rj] = __fmaf_rn(ks[ri], qv[rj], acc[ri][rj]);
        }

        // inserts: ascending j within thread; strict > gate (validated tie-break)
        #pragma unroll
        for (int rj = 0; rj < 8; rj++) {
            int j = jt + tidj * 8 + rj;
            #pragma unroll
            for (int ri = 0; ri < 4; ri++) {
                float s = fmaxf(acc[ri][rj], 0.f);
                if (s > vv[ri]) {
                    int base = ri * 9;
                    tlv[base + 8] = s; tlj[base + 8] = j;
                    #pragma unroll 1
                    for (int z = 8; z >= 1; z--) {
                        if (tlv[base + z] > tlv[base + z - 1]) {
                            float tv = tlv[base + z - 1];
                            tlv[base + z - 1] = tlv[base + z]; tlv[base + z] = tv;
                            int tj2 = tlj[base + z - 1];
                            tlj[base + z - 1] = tlj[base + z]; tlj[base + z] = tj2;
                        } else break;
                    }
                    vv[ri] = tlv[base + 8];
                }
            }
        }
    }

    // write partial lists
    #pragma unroll
    for (int ri = 0; ri < 4; ri++) {
        int row = i0 + tidi * 4 + ri;
        size_t g = ((bT + row) * 8 + tidj) * 9;
        #pragma unroll 1
        for (int z = 0; z < 9; z++) {
            g_pv[g + z] = tlv[ri * 9 + z];
            g_pj[g + z] = tlj[ri * 9 + z];
        }
    }
}

// ---------------------------------------------------------------------------
// Kernel 2b: merge 8 exact partial top-9 lists per row -> lex top-9.
// Lex compare (val desc, idx asc) == jax top_k semantics (validated R8).
// ---------------------------------------------------------------------------
__global__ __launch_bounds__(256) void sim_merge_kernel()
{
    const int    b   = blockIdx.y;
    const int    row = blockIdx.x * 256 + threadIdx.x;
    const size_t bT  = (size_t)b * T;

    float v[9]; int jx[9];
    #pragma unroll
    for (int z = 0; z < 9; z++) { v[z] = -1.f; jx[z] = 0x7FFFFFFF; }

    for (int src = 0; src < 8; src++) {
        size_t g = ((bT + row) * 8 + src) * 9;
        for (int e = 0; e < 9; e++) {
            float s = g_pv[g + e];
            int   j = g_pj[g + e];
            if ((s > v[8]) || (s == v[8] && j < jx[8])) {
                v[8] = s; jx[8] = j;
                #pragma unroll
                for (int z = 8; z >= 1; z--) {
                    if ((v[z] > v[z-1]) || (v[z] == v[z-1] && jx[z] < jx[z-1])) {
                        float tv = v[z-1]; v[z-1] = v[z]; v[z] = tv;
                        int tj2 = jx[z-1]; jx[z-1] = jx[z]; jx[z] = tj2;
                    }
                }
            }
        }
    }

    int* op = g_idx + (bT + row) * KNN;
    #pragma unroll
    for (int z = 0; z < 9; z++) op[z] = jx[z];
}

// ---------------------------------------------------------------------------
// Kernel 3: gather v + 1x1 conv (576 -> 64) + bias (R4 version, 92us)
// ---------------------------------------------------------------------------
__global__ __launch_bounds__(128) void gather_conv_kernel(
    const float* __restrict__ conv_b,
    float* __restrict__ out)
{
    __shared__ float  Ws[C * C];
    __shared__ float4 Vs[4][16][33];

    const int b   = blockIdx.y;
    const int tid = threadIdx.x;
    const int w   = tid >> 5;
    const int l   = tid & 31;
    const int i   = blockIdx.x * 128 + tid;

    u64 accp[32];
    #pragma unroll
    for (int o2 = 0; o2 < 32; o2++) accp[o2] = 0ull;

    const int base = (b * T + i) * KNN;

    for (int kk = 0; kk < KNN; kk++) {
        __syncthreads();
        {
            const float4* wsrc = (const float4*)(g_wP + kk * C * C);
            float4* wdst = (float4*)Ws;
            #pragma unroll
            for (int r = 0; r < 8; r++)
                wdst[r * 128 + tid] = wsrc[r * 128 + tid];
        }

        int j = g_idx[base + kk];

        #pragma unroll
        for (int rp = 0; rp < 32; rp += 2) {
            int r  = rp + (l >> 4);
            int c4 = l & 15;
            int jr = __shfl_sync(0xffffffffu, j, r);
            float4 vv = ((const float4*)(g_vT + ((size_t)b * T + jr) * C))[c4];
            Vs[w][c4][r] = vv;
        }
        __syncthreads();

        #pragma unroll
        for (int c4 = 0; c4 < 16; c4++) {
            float4 xv = Vs[w][c4][l];
            float xs[4] = {xv.x, xv.y, xv.z, xv.w};
            #pragma unroll
            for (int e = 0; e < 4; e++) {
                u64 xd = pk2(xs[e], xs[e]);
                const ulonglong2* wr = (const ulonglong2*)(Ws + (c4 * 4 + e) * C);
                #pragma unroll
                for (int o4 = 0; o4 < 16; o4++) {
                    ulonglong2 wp = wr[o4];
                    accp[2*o4+0] = fma2(xd, wp.x, accp[2*o4+0]);
                    accp[2*o4+1] = fma2(xd, wp.y, accp[2*o4+1]);
                }
            }
        }
    }

    #pragma unroll
    for (int o2 = 0; o2 < 32; o2++) {
        float f0, f1;
        unpk(accp[o2], f0, f1);
        out[((size_t)(b * C + 2*o2 + 0)) * T + i] = f0 + __ldg(&conv_b[2*o2 + 0]);
        out[((size_t)(b * C + 2*o2 + 1)) * T + i] = f1 + __ldg(&conv_b[2*o2 + 1]);
    }
}

// ---------------------------------------------------------------------------
extern "C" void kernel_launch(void* const* d_in, const int* in_sizes, int n_in,
                              void* d_out, int out_size)
{
    const float* x      = (const float*)d_in[0];
    const float* Wq     = (const float*)d_in[1];
    const float* Wk     = (const float*)d_in[2];
    const float* Wv     = (const float*)d_in[3];
    const float* conv_w = (const float*)d_in[4];
    const float* conv_b = (const float*)d_in[5];
    float* out          = (float*)d_out;

    cudaFuncSetAttribute(sim_sweep_kernel,
                         cudaFuncAttributeMaxDynamicSharedMemorySize, SIM_SMEM);

    permute_w_kernel<<<(KNN * C * C + 255) / 256, 256>>>(conv_w);
    proj_kernel<<<dim3(T / 128, B), 128>>>(x, Wq, Wk, Wv);
    sim_sweep_kernel<<<dim3(T / 256, B), 512, SIM_SMEM>>>();
    sim_merge_kernel<<<dim3(T / 256, B), 256>>>();
    gather_conv_kernel<<<dim3(T / 128, B), 128>>>(conv_b, out);
}

// round 16
// speedup vs baseline: 17.4797x; 17.4797x over previous
#include <cuda_runtime.h>
#include <cuda_bf16.h>
#include <stdint.h>
#include <math.h>

#define B      8
#define C      64
#define T      4096
#define KNN    9
#define NTILES (T / 128)      // 32 j-tiles of 128
#define NLANE  12             // per-(thread,row) approx list depth
#define MMERGE 24             // merged per-row shortlist depth
#define ERRB   0.006f         // >= rigorous bf16 product bound 2^-8 = 0.0039

typedef unsigned long long u64;
typedef unsigned int       u32;

// Scratch (allocation-free: __device__ globals)
__device__ float g_qT[B * T * C];                         // normalized q fp32 [b][t][c]
__device__ float g_kT[B * T * C];                         // normalized k fp32
__device__ float g_vT[B * T * C];                         // v fp32
__device__ __align__(16) __nv_bfloat16 g_qB[B * T * C];   // bf16 copy of g_qT
__device__ __align__(16) __nv_bfloat16 g_kB[B * T * C];   // bf16 copy of g_kT
__device__ float g_wP[KNN * C * C];                       // conv_w permuted [kk][cc][o]
__device__ int   g_idx[B * T * KNN];                      // top-9 indices per (b,i)

// smem layout constants (bytes, within dynamic smem) -- sim kernel
#define A_OFF    0             // 128 rows x 144B = 18432
#define B0_OFF   18432         // B tile buffer 0 (18432)
#define B1_OFF   36864         // B tile buffer 1 (18432)
#define LIST_OFF 0             // [8 warps][32 lanes][2][12] u64 = 49152 (overlay, post-mainloop)
#define MK_OFF   49152         // [8][16][24] u64 = 24576 (post-mainloop)
#define ACUT_OFF 73728         // [8][16] float = 512
#define SMEM_SZ  74240
#define STG_STRIDE 68          // floats per staged row (rerank)

// ---------------------------------------------------------------------------
// helpers
// ---------------------------------------------------------------------------
__device__ __forceinline__ u32 smem_u32(const void* p) {
    u32 a;
    asm("{ .reg .u64 t; cvta.to.shared.u64 t, %1; cvt.u32.u64 %0, t; }"
        : "=r"(a) : "l"(p));
    return a;
}
__device__ __forceinline__ u64 pk2(float lo, float hi) {
    u64 r; asm("mov.b64 %0, {%1, %2};" : "=l"(r) : "f"(lo), "f"(hi)); return r;
}
__device__ __forceinline__ u64 fma2(u64 a, u64 b, u64 c) {
    u64 d; asm("fma.rn.f32x2 %0, %1, %2, %3;" : "=l"(d) : "l"(a), "l"(b), "l"(c));
    return d;
}
__device__ __forceinline__ void unpk(u64 v, float& lo, float& hi) {
    asm("mov.b64 {%0, %1}, %2;" : "=f"(lo), "=f"(hi) : "l"(v));
}
__device__ __forceinline__ void ldm4(u32* r, u32 addr) {
    asm volatile("ldmatrix.sync.aligned.m8n8.x4.shared.b16 {%0,%1,%2,%3}, [%4];"
                 : "=r"(r[0]), "=r"(r[1]), "=r"(r[2]), "=r"(r[3]) : "r"(addr));
}
__device__ __forceinline__ void mma16816(float* c, const u32* a, const u32* b) {
    asm volatile("mma.sync.aligned.m16n8k16.row.col.f32.bf16.bf16.f32 "
                 "{%0,%1,%2,%3}, {%4,%5,%6,%7}, {%8,%9}, {%0,%1,%2,%3};"
                 : "+f"(c[0]), "+f"(c[1]), "+f"(c[2]), "+f"(c[3])
                 : "r"(a[0]), "r"(a[1]), "r"(a[2]), "r"(a[3]),
                   "r"(b[0]), "r"(b[1]));
}
__device__ __forceinline__ void cpa16(u32 daddr, const void* gptr) {
    asm volatile("cp.async.cg.shared.global [%0], [%1], 16;"
                 :: "r"(daddr), "l"(gptr) : "memory");
}
#define CPA_COMMIT() asm volatile("cp.async.commit_group;" ::: "memory")
#define CPA_WAIT0()  asm volatile("cp.async.wait_group 0;" ::: "memory")

// ---------------------------------------------------------------------------
// Kernel 0: permute conv_w[o][cc*9+kk] -> wP[kk][cc][o]
// ---------------------------------------------------------------------------
__global__ void permute_w_kernel(const float* __restrict__ conv_w) {
    int s = blockIdx.x * 256 + threadIdx.x;
    if (s < KNN * C * C) {
        int o  = s & 63;
        int cc = (s >> 6) & 63;
        int kk = s >> 12;
        g_wP[s] = conv_w[o * (C * KNN) + cc * KNN + kk];
    }
}

// ---------------------------------------------------------------------------
// Kernel 1: q/k/v projections + L2 normalize (k,q); fp32 + bf16 outputs.
// (byte-identical to R8; validated at rel_err 5.3e-7)
// ---------------------------------------------------------------------------
__global__ __launch_bounds__(128) void proj_kernel(
    const float* __restrict__ x,
    const float* __restrict__ Wq,
    const float* __restrict__ Wk,
    const float* __restrict__ Wv)
{
    __shared__ float Xs[C][128];
    __shared__ float Ws[C][C];

    const int b   = blockIdx.y;
    const int t0  = blockIdx.x * 128;
    const int tid = threadIdx.x;

    const float* xb = x + (size_t)b * C * T;
    for (int c = 0; c < C; c++)
        Xs[c][tid] = xb[c * T + t0 + tid];

    for (int m = 0; m < 3; m++) {
        const float* W = (m == 0) ? Wq : ((m == 1) ? Wk : Wv);
        float* dstbase = (m == 0) ? g_qT : ((m == 1) ? g_kT : g_vT);

        __syncthreads();
        for (int s = tid; s < C * C; s += 128) {
            int c = s >> 6, d = s & 63;
            Ws[c][d] = W[d * C + c];
        }
        __syncthreads();

        float acc[C];
        #pragma unroll
        for (int d = 0; d < C; d++) acc[d] = 0.f;

        for (int c = 0; c < C; c++) {
            float xv = Xs[c][tid];
            const float4* wr = (const float4*)Ws[c];
            #pragma unroll
            for (int d4 = 0; d4 < 16; d4++) {
                float4 w = wr[d4];
                acc[4*d4+0] = __fmaf_rn(w.x, xv, acc[4*d4+0]);
                acc[4*d4+1] = __fmaf_rn(w.y, xv, acc[4*d4+1]);
                acc[4*d4+2] = __fmaf_rn(w.z, xv, acc[4*d4+2]);
                acc[4*d4+3] = __fmaf_rn(w.w, xv, acc[4*d4+3]);
            }
        }

        if (m < 2) {
            float ss = 0.f;
            #pragma unroll
            for (int d = 0; d < C; d++)
                ss = __fadd_rn(ss, __fmul_rn(acc[d], acc[d]));
            float n = fmaxf(sqrtf(ss), 1e-12f);
            #pragma unroll
            for (int d = 0; d < C; d++)
                acc[d] = __fdiv_rn(acc[d], n);
        }

        float4* dst = (float4*)(dstbase + ((size_t)b * T + t0 + tid) * C);
        #pragma unroll
        for (int d4 = 0; d4 < 16; d4++)
            dst[d4] = make_float4(acc[4*d4+0], acc[4*d4+1], acc[4*d4+2], acc[4*d4+3]);

        if (m < 2) {
            __nv_bfloat16* bb = (m == 0) ? g_qB : g_kB;
            __nv_bfloat162* bd = (__nv_bfloat162*)(bb + ((size_t)b * T + t0 + tid) * C);
            #pragma unroll
            for (int d2 = 0; d2 < 32; d2++)
                bd[d2] = __floats2bfloat162_rn(acc[2*d2], acc[2*d2+1]);
        }
    }
}

// ---------------------------------------------------------------------------
// Lex Top9: value desc, index asc on ties (== jax top_k). Any insert order.
// ---------------------------------------------------------------------------
struct Top9 {
    float v0,v1,v2,v3,v4,v5,v6,v7,v8;
    int   j0,j1,j2,j3,j4,j5,j6,j7,j8;
    __device__ __forceinline__ void init() {
        v0=v1=v2=v3=v4=v5=v6=v7=v8 = -1.f;
        j0=j1=j2=j3=j4=j5=j6=j7=j8 = 0x7FFFFFFF;
    }
    __device__ __forceinline__ void insert(float s, int j) {
        if ((s > v8) || (s == v8 && j < j8)) {
            v8 = s; j8 = j;
            #define _LSW(va,ja,vb,jb) if (((vb) > (va)) || ((vb) == (va) && (jb) < (ja))) { \
                float tv=(va); (va)=(vb); (vb)=tv; int tj=(ja); (ja)=(jb); (jb)=tj; }
            _LSW(v7,j7,v8,j8); _LSW(v6,j6,v7,j7); _LSW(v5,j5,v6,j6);
            _LSW(v4,j4,v5,j5); _LSW(v3,j3,v4,j4); _LSW(v2,j2,v3,j3);
            _LSW(v1,j1,v2,j2); _LSW(v0,j0,v1,j1);
            #undef _LSW
        }
    }
    __device__ __forceinline__ void store(int* op) {
        op[0]=j0; op[1]=j1; op[2]=j2; op[3]=j3; op[4]=j4;
        op[5]=j5; op[6]=j6; op[7]=j7; op[8]=j8;
    }
};

__device__ __forceinline__ float exact_dot_g(const float* __restrict__ kr,
                                             const float* __restrict__ qrow)
{
    const float4* q = (const float4*)qrow;
    float s = 0.f;
    #pragma unroll
    for (int c4 = 0; c4 < 16; c4++) {
        float4 qq = __ldg(&q[c4]);
        s = __fmaf_rn(kr[4*c4+0], qq.x, s);
        s = __fmaf_rn(kr[4*c4+1], qq.y, s);
        s = __fmaf_rn(kr[4*c4+2], qq.z, s);
        s = __fmaf_rn(kr[4*c4+3], qq.w, s);
    }
    return s;
}

#define PROC_SCORE(val, KL, MN, jj) do {                                      \
    float s_ = fmaxf((val), 0.f) + 1.0f;                                      \
    if (s_ > (MN)) {                                                          \
        u64 key_ = ((u64)__float_as_uint(s_) << 32) | (u32)(0xFFFFu - (u32)(jj)); \
        KL[11] = key_;                                                        \
        _Pragma("unroll")                                                     \
        for (int z_ = 10; z_ >= 0; z_--)                                      \
            if (KL[z_+1] > KL[z_]) { u64 t_ = KL[z_]; KL[z_] = KL[z_+1]; KL[z_+1] = t_; } \
        MN = __uint_as_float((u32)(KL[11] >> 32));                            \
    } } while (0)

// ---------------------------------------------------------------------------
// Kernel 2: bf16 mma.sync prefilter -> per-row top-24 shortlist ->
//           exact fp32 re-rank -> lex Top9 (+ sound margin check/fallback).
// R8 structure; B-tile staging converted to cp.async double buffering.
// ---------------------------------------------------------------------------
__global__ __launch_bounds__(256) void sim_topk_mma_kernel()
{
    extern __shared__ __align__(16) char dynsmem[];

    const int b    = blockIdx.y;
    const int tid  = threadIdx.x;
    const int w    = tid >> 5;
    const int lane = tid & 31;
    const int i0   = blockIdx.x * 128;

    const u32 sb = smem_u32(dynsmem);

    // ---- stage A: 128 k-rows bf16 -> smem rows of 144B ----
    {
        const uint4* src = (const uint4*)(g_kB + ((size_t)b * T + i0) * C);
        #pragma unroll
        for (int it = 0; it < 4; it++) {
            int idx = it * 256 + tid;
            int row = idx >> 3, ch = idx & 7;
            uint4 v = __ldg(src + row * 8 + ch);
            *(uint4*)(dynsmem + A_OFF + row * 144 + ch * 16) = v;
        }
    }

    // ---- issue cp.async for B tile 0 into B0 (overlaps A-sync latency) ----
    {
        const uint4* src = (const uint4*)(g_qB + (size_t)b * T * C);
        #pragma unroll
        for (int it = 0; it < 4; it++) {
            int idx = it * 256 + tid;
            int row = idx >> 3, ch = idx & 7;
            cpa16(sb + B0_OFF + (u32)(row * 144 + ch * 16), src + row * 8 + ch);
        }
        CPA_COMMIT();
    }
    __syncthreads();

    // ---- A fragments (warp's 16 rows, 4 k-steps) ----
    u32 afr[4][4];
    {
        u32 abase = sb + A_OFF + (w * 16 + (lane & 15)) * 144 + (lane >> 4) * 16;
        #pragma unroll
        for (int ks = 0; ks < 4; ks++) ldm4(afr[ks], abase + ks * 32);
    }

    u64 kl0[NLANE], kl1[NLANE];
    float mn0 = 0.f, mn1 = 0.f;
    #pragma unroll
    for (int m = 0; m < NLANE; m++) { kl0[m] = 0ull; kl1[m] = 0ull; }

    const int jrow  = (lane & 7) + ((lane >> 4) << 3);
    const int khalf = (lane >> 3) & 1;
    const int q0    = 2 * (lane & 3);

    for (int t = 0; t < NTILES; t++) {
        CPA_WAIT0();
        __syncthreads();   // tile t resident; nobody still reads buf (t+1)&1

        if (t + 1 < NTILES) {   // stage tile t+1 into the other buffer
            const uint4* src = (const uint4*)(g_qB + ((size_t)b * T + (size_t)(t + 1) * 128) * C);
            u32 dofs = ((t + 1) & 1) ? B1_OFF : B0_OFF;
            #pragma unroll
            for (int it = 0; it < 4; it++) {
                int idx = it * 256 + tid;
                int row = idx >> 3, ch = idx & 7;
                cpa16(sb + dofs + (u32)(row * 144 + ch * 16), src + row * 8 + ch);
            }
            CPA_COMMIT();
        }

        const u32 bofs = (t & 1) ? B1_OFF : B0_OFF;

        #pragma unroll 2
        for (int chunk = 0; chunk < 8; chunk++) {
            u32 bbase = sb + bofs + (chunk * 16 + jrow) * 144 + khalf * 16;
            float a0[4] = {0.f, 0.f, 0.f, 0.f};
            float a1[4] = {0.f, 0.f, 0.f, 0.f};
            #pragma unroll
            for (int ks = 0; ks < 4; ks++) {
                u32 bb[4];
                ldm4(bb, bbase + ks * 32);
                mma16816(a0, afr[ks], bb + 0);
                mma16816(a1, afr[ks], bb + 2);
            }
            int jb = t * 128 + chunk * 16 + q0;
            PROC_SCORE(a0[0], kl0, mn0, jb + 0);
            PROC_SCORE(a0[1], kl0, mn0, jb + 1);
            PROC_SCORE(a0[2], kl1, mn1, jb + 0);
            PROC_SCORE(a0[3], kl1, mn1, jb + 1);
            PROC_SCORE(a1[0], kl0, mn0, jb + 8);
            PROC_SCORE(a1[1], kl0, mn0, jb + 9);
            PROC_SCORE(a1[2], kl1, mn1, jb + 8);
            PROC_SCORE(a1[3], kl1, mn1, jb + 9);
        }
    }

    // ---- dump lists to smem (overlays A/B region; mainloop is done) ----
    __syncthreads();
    u64* LST = (u64*)(dynsmem + LIST_OFF);
    {
        u64* my = LST + (size_t)(w * 32 + lane) * (2 * NLANE);
        #pragma unroll
        for (int m = 0; m < NLANE; m++) { my[m] = kl0[m]; my[NLANE + m] = kl1[m]; }
    }
    __syncwarp();

    u64*   MK  = (u64*)(dynsmem + MK_OFF);
    float* ACT = (float*)(dynsmem + ACUT_OFF);
    if ((lane & 1) == 0) {
        int r    = lane >> 2;
        int half = (lane >> 1) & 1;
        int rrow = r + half * 8;
        u64* mk  = MK + (size_t)(w * 16 + rrow) * MMERGE;
        #pragma unroll
        for (int m = 0; m < MMERGE; m++) mk[m] = 0ull;
        float acut = 0.f;
        for (int src = 0; src < 4; src++) {
            const u64* L = LST + (size_t)(w * 32 + r * 4 + src) * (2 * NLANE) + half * NLANE;
            acut = fmaxf(acut, __uint_as_float((u32)(L[NLANE - 1] >> 32)));
            for (int e = 0; e < NLANE; e++) {
                u64 key = L[e];
                if (!(key >> 32)) break;
                if (key <= mk[MMERGE - 1]) continue;
                mk[MMERGE - 1] = key;
                for (int z = MMERGE - 2; z >= 0; z--) {
                    if (mk[z + 1] > mk[z]) { u64 tk = mk[z]; mk[z] = mk[z + 1]; mk[z + 1] = tk; }
                    else break;
                }
            }
        }
        acut = fmaxf(acut, __uint_as_float((u32)(mk[MMERGE - 1] >> 32)));
        ACT[w * 16 + rrow] = acut;
    }
    __syncwarp();

    float kr[C];
    if (lane < 16) {
        const float4* kp4 = (const float4*)(g_kT + ((size_t)b * T + i0 + w * 16 + lane) * C);
        #pragma unroll
        for (int c4 = 0; c4 < 16; c4++) {
            float4 k4 = __ldg(&kp4[c4]);
            kr[4*c4+0] = k4.x; kr[4*c4+1] = k4.y;
            kr[4*c4+2] = k4.z; kr[4*c4+3] = k4.w;
        }
    }

    Top9 t9;
    t9.init();
    float* stg = (float*)(dynsmem + (size_t)w * 6144);

    for (int m = 0; m < MMERGE; m++) {
        __syncwarp();
        #pragma unroll
        for (int it = 0; it < 8; it++) {
            int idx = it * 32 + lane;
            int r = idx >> 4, c4 = idx & 15;
            u64 key = MK[(size_t)(w * 16 + r) * MMERGE + m];
            int jc = (key >> 32) ? (int)(0xFFFFu - (u32)(key & 0xFFFFu)) : 0;
            float4 qv = __ldg((const float4*)(g_qT + ((size_t)b * T + jc) * C) + c4);
            *(float4*)(stg + r * STG_STRIDE + c4 * 4) = qv;
        }
        __syncwarp();
        if (lane < 16) {
            u64 key = MK[(size_t)(w * 16 + lane) * MMERGE + m];
            if (key >> 32) {
                int jc = (int)(0xFFFFu - (u32)(key & 0xFFFFu));
                const float4* qs = (const float4*)(stg + lane * STG_STRIDE);
                float s = 0.f;
                #pragma unroll
                for (int c4 = 0; c4 < 16; c4++) {
                    float4 q = qs[c4];
                    s = __fmaf_rn(kr[4*c4+0], q.x, s);
                    s = __fmaf_rn(kr[4*c4+1], q.y, s);
                    s = __fmaf_rn(kr[4*c4+2], q.z, s);
                    s = __fmaf_rn(kr[4*c4+3], q.w, s);
                }
                t9.insert(fmaxf(s, 0.f), jc);
            }
        }
    }

    if (lane < 16) {
        float acut = ACT[w * 16 + lane];
        if (acut - 1.0f + ERRB >= t9.v8) {
            t9.init();
            const float* qb = g_qT + (size_t)b * T * C;
            for (int j = 0; j < T; j++) {
                float s = fmaxf(exact_dot_g(kr, qb + (size_t)j * C), 0.f);
                t9.insert(s, j);
            }
        }
        t9.store(g_idx + ((size_t)b * T + i0 + w * 16 + lane) * KNN);
    }
}

// ---------------------------------------------------------------------------
// Kernel 3: gather v + 1x1 conv (576 -> 64) + bias (R4 version, 92us)
// ---------------------------------------------------------------------------
__global__ __launch_bounds__(128) void gather_conv_kernel(
    const float* __restrict__ conv_b,
    float* __restrict__ out)
{
    __shared__ float  Ws[C * C];
    __shared__ float4 Vs[4][16][33];

    const int b   = blockIdx.y;
    const int tid = threadIdx.x;
    const int w   = tid >> 5;
    const int l   = tid & 31;
    const int i   = blockIdx.x * 128 + tid;

    u64 accp[32];
    #pragma unroll
    for (int o2 = 0; o2 < 32; o2++) accp[o2] = 0ull;

    const int base = (b * T + i) * KNN;

    for (int kk = 0; kk < KNN; kk++) {
        __syncthreads();
        {
            const float4* wsrc = (const float4*)(g_wP + kk * C * C);
            float4* wdst = (float4*)Ws;
            #pragma unroll
            for (int r = 0; r < 8; r++)
                wdst[r * 128 + tid] = wsrc[r * 128 + tid];
        }

        int j = g_idx[base + kk];

        #pragma unroll
        for (int rp = 0; rp < 32; rp += 2) {
            int r  = rp + (l >> 4);
            int c4 = l & 15;
            int jr = __shfl_sync(0xffffffffu, j, r);
            float4 vv = ((const float4*)(g_vT + ((size_t)b * T + jr) * C))[c4];
            Vs[w][c4][r] = vv;
        }
        __syncthreads();

        #pragma unroll
        for (int c4 = 0; c4 < 16; c4++) {
            float4 xv = Vs[w][c4][l];
            float xs[4] = {xv.x, xv.y, xv.z, xv.w};
            #pragma unroll
            for (int e = 0; e < 4; e++) {
                u64 xd = pk2(xs[e], xs[e]);
                const ulonglong2* wr = (const ulonglong2*)(Ws + (c4 * 4 + e) * C);
                #pragma unroll
                for (int o4 = 0; o4 < 16; o4++) {
                    ulonglong2 wp = wr[o4];
                    accp[2*o4+0] = fma2(xd, wp.x, accp[2*o4+0]);
                    accp[2*o4+1] = fma2(xd, wp.y, accp[2*o4+1]);
                }
            }
        }
    }

    #pragma unroll
    for (int o2 = 0; o2 < 32; o2++) {
        float f0, f1;
        unpk(accp[o2], f0, f1);
        out[((size_t)(b * C + 2*o2 + 0)) * T + i] = f0 + __ldg(&conv_b[2*o2 + 0]);
        out[((size_t)(b * C + 2*o2 + 1)) * T + i] = f1 + __ldg(&conv_b[2*o2 + 1]);
    }
}

// ---------------------------------------------------------------------------
extern "C" void kernel_launch(void* const* d_in, const int* in_sizes, int n_in,
                              void* d_out, int out_size)
{
    const float* x      = (const float*)d_in[0];
    const float* Wq     = (const float*)d_in[1];
    const float* Wk     = (const float*)d_in[2];
    const float* Wv     = (const float*)d_in[3];
    const float* conv_w = (const float*)d_in[4];
    const float* conv_b = (const float*)d_in[5];
    float* out          = (float*)d_out;

    cudaFuncSetAttribute(sim_topk_mma_kernel,
                         cudaFuncAttributeMaxDynamicSharedMemorySize, SMEM_SZ);

    permute_w_kernel<<<(KNN * C * C + 255) / 256, 256>>>(conv_w);
    proj_kernel<<<dim3(T / 128, B), 128>>>(x, Wq, Wk, Wv);
    sim_topk_mma_kernel<<<dim3(T / 128, B), 256, SMEM_SZ>>>();
    gather_conv_kernel<<<dim3(T / 128, B), 128>>>(conv_b, out);
}